// round 1
// baseline (speedup 1.0000x reference)
#include <cuda_runtime.h>
#include <cuda_bf16.h>

#define R   2
#define TX  32
#define TY  4
#define TZ  4
#define SXT (TX + 2*R)   // 36
#define SYT (TY + 2*R)   // 8
#define SZT (TZ + 2*R)   // 8
#define NDIM 128
#define NVOX (NDIM*NDIM*NDIM)
#define NTHREADS (TX*TY*TZ)

__device__ __forceinline__ float ex2f(float x) {
    float y;
    asm("ex2.approx.ftz.f32 %0, %1;" : "=f"(y) : "f"(x));
    return y;
}

__global__ __launch_bounds__(NTHREADS)
void bilateral3d_kernel(const float* __restrict__ in,
                        float* __restrict__ out,
                        const float* __restrict__ p_sx,
                        const float* __restrict__ p_sy,
                        const float* __restrict__ p_sz,
                        const float* __restrict__ p_cs)
{
    __shared__ float tile[SZT][SYT][SXT];   // 8*8*36*4 = 9216 B

    const float LOG2E = 1.4426950408889634f;
    const float sx = *p_sx, sy = *p_sy, sz = *p_sz, cs = *p_cs;
    const float ax = -LOG2E / (2.0f * sx * sx);
    const float ay = -LOG2E / (2.0f * sy * sy);
    const float az = -LOG2E / (2.0f * sz * sz);
    const float cc = -LOG2E / (2.0f * cs * cs);

    const int x0 = blockIdx.x * TX;
    const int y0 = blockIdx.y * TY;
    const int zb = blockIdx.z;
    const int z0    = (zb & ((NDIM/TZ) - 1)) * TZ;   // 32 z-tiles per batch
    const int batch =  zb / (NDIM/TZ);
    const float* src = in + (size_t)batch * NVOX;

    // ---- cooperative tile load with sentinel halo ----
    const float BIG = 1e18f;   // forces range weight to exact 0 for OOB taps
    const int tid = threadIdx.x + TX * (threadIdx.y + TY * threadIdx.z);
    float* tflat = &tile[0][0][0];
    #pragma unroll
    for (int i = tid; i < SZT*SYT*SXT; i += NTHREADS) {
        int lx = i % SXT;
        int t  = i / SXT;
        int ly = t % SYT;
        int lz = t / SYT;
        int gx = x0 + lx - R;
        int gy = y0 + ly - R;
        int gz = z0 + lz - R;
        float v = BIG;
        if ((unsigned)gx < NDIM && (unsigned)gy < NDIM && (unsigned)gz < NDIM)
            v = src[((size_t)gz * NDIM + gy) * NDIM + gx];
        tflat[i] = v;
    }
    __syncthreads();

    // ---- per-thread spatial log2-weights (dx^2 in {0,1,4}) ----
    float wx[5], wy[5], wz[5];
    #pragma unroll
    for (int i = 0; i < 5; i++) {
        float d  = (float)(i - R);
        float d2 = d * d;
        wx[i] = d2 * ax;
        wy[i] = d2 * ay;
        wz[i] = d2 * az;
    }

    const int lx = threadIdx.x, ly = threadIdx.y, lz = threadIdx.z;
    const float xc = tile[lz + R][ly + R][lx + R];

    float num = 0.0f, den = 0.0f;
    #pragma unroll
    for (int dz = 0; dz < 5; dz++) {
        #pragma unroll
        for (int dy = 0; dy < 5; dy++) {
            const float wyz = wy[dy] + wz[dz];
            #pragma unroll
            for (int dx = 0; dx < 5; dx++) {
                float xk  = tile[lz + dz][ly + dy][lx + dx];
                float lgw = wx[dx] + wyz;
                float d   = xc - xk;
                float w   = ex2f(fmaf(d * d, cc, lgw));
                num = fmaf(w, xk, num);
                den += w;
            }
        }
    }

    const size_t o = (size_t)batch * NVOX
                   + ((size_t)(z0 + lz) * NDIM + (y0 + ly)) * NDIM + (x0 + lx);
    out[o] = __fdividef(num, den);
}

extern "C" void kernel_launch(void* const* d_in, const int* in_sizes, int n_in,
                              void* d_out, int out_size)
{
    const float* img = (const float*)d_in[0];
    const float* psx = (const float*)d_in[1];
    const float* psy = (const float*)d_in[2];
    const float* psz = (const float*)d_in[3];
    const float* pcs = (const float*)d_in[4];
    float* outp = (float*)d_out;

    const int batches = in_sizes[0] / NVOX;   // 2 for this problem
    dim3 block(TX, TY, TZ);
    dim3 grid(NDIM / TX, NDIM / TY, (NDIM / TZ) * batches);
    bilateral3d_kernel<<<grid, block>>>(img, outp, psx, psy, psz, pcs);
}

// round 2
// speedup vs baseline: 1.0422x; 1.0422x over previous
#include <cuda_runtime.h>
#include <cuda_bf16.h>

#define R   2
#define TX  32
#define TY  4
#define TZ  4
#define SXT (TX + 2*R)   // 36
#define SYT (TY + 2*R)   // 8
#define SZT (TZ + 2*R)   // 8
#define NDIM 128
#define NVOX (NDIM*NDIM*NDIM)
#define NTHREADS (TX*TY*TZ)

__device__ __forceinline__ float ex2f(float x) {
    float y;
    asm("ex2.approx.ftz.f32 %0, %1;" : "=f"(y) : "f"(x));
    return y;
}

__global__ __launch_bounds__(NTHREADS)
void bilateral3d_kernel(const float* __restrict__ in,
                        float* __restrict__ out,
                        const float* __restrict__ p_sx,
                        const float* __restrict__ p_sy,
                        const float* __restrict__ p_sz,
                        const float* __restrict__ p_cs)
{
    __shared__ float tile[SZT][SYT][SXT];   // 9216 B

    const float LOG2E = 1.4426950408889634f;
    const float sx = *p_sx, sy = *p_sy, sz = *p_sz, cs = *p_cs;
    const float ax  = -LOG2E / (2.0f * sx * sx);   // log2-domain spatial weights
    const float ay  = -LOG2E / (2.0f * sy * sy);
    const float az  = -LOG2E / (2.0f * sz * sz);
    const float ssq =  LOG2E / (2.0f * cs * cs);   // -cc
    const float s    = sqrtf(ssq);
    const float negs = -s;

    const int x0 = blockIdx.x * TX;
    const int y0 = blockIdx.y * TY;
    const int zb = blockIdx.z;
    const int z0    = (zb & ((NDIM/TZ) - 1)) * TZ;
    const int batch =  zb / (NDIM/TZ);
    const float* src = in + (size_t)batch * NVOX;

    // ---- cooperative tile load with sentinel halo ----
    const float BIG = 1e18f;   // OOB sentinel: ds^2 ~ 1e36 -> ex2 -> exact 0
    const int tid = threadIdx.x + TX * (threadIdx.y + TY * threadIdx.z);
    float* tflat = &tile[0][0][0];
    #pragma unroll
    for (int i = tid; i < SZT*SYT*SXT; i += NTHREADS) {
        int lx = i % SXT;
        int t  = i / SXT;
        int ly = t % SYT;
        int lz = t / SYT;
        int gx = x0 + lx - R;
        int gy = y0 + ly - R;
        int gz = z0 + lz - R;
        float v = BIG;
        if ((unsigned)gx < NDIM && (unsigned)gy < NDIM && (unsigned)gz < NDIM)
            v = src[((size_t)gz * NDIM + gy) * NDIM + gx];
        tflat[i] = v;
    }
    __syncthreads();

    // spatial log2-weights per axis: d2 in {4,1,0}
    const float ax1 = ax, ax4 = 4.0f * ax;
    float wy[5], wz[5];
    #pragma unroll
    for (int i = 0; i < 5; i++) {
        float d  = (float)(i - R);
        float d2 = d * d;
        wy[i] = d2 * ay;
        wz[i] = d2 * az;
    }

    const int lx = threadIdx.x, ly = threadIdx.y, lz = threadIdx.z;
    const float xcs = tile[lz + R][ly + R][lx + R] * s;   // xc * s

    float num = 0.0f, den = 0.0f;

    #define TAP(dz_, dy_, dx_, b_)                                   \
        {                                                            \
            float xk  = tile[lz + (dz_)][ly + (dy_)][lx + (dx_)];    \
            float ds  = fmaf(xk, negs, xcs);   /* (xc-xk)*s */       \
            float arg = fmaf(ds, -ds, (b_));   /* cc*d^2 + lgw */    \
            float w   = ex2f(arg);                                   \
            num = fmaf(w, xk, num);                                  \
            den += w;                                                \
        }

    #pragma unroll
    for (int dz = 0; dz < 5; dz++) {
        #pragma unroll
        for (int dy = 0; dy < 5; dy++) {
            const float b0 = wy[dy] + wz[dz];  // dx offset 0  (center)
            const float b1 = b0 + ax1;         // |dx|=1
            const float b4 = b0 + ax4;         // |dx|=2
            TAP(dz, dy, 0, b4)
            TAP(dz, dy, 1, b1)
            TAP(dz, dy, 2, b0)
            TAP(dz, dy, 3, b1)
            TAP(dz, dy, 4, b4)
        }
    }
    #undef TAP

    const size_t o = (size_t)batch * NVOX
                   + ((size_t)(z0 + lz) * NDIM + (y0 + ly)) * NDIM + (x0 + lx);
    out[o] = __fdividef(num, den);
}

extern "C" void kernel_launch(void* const* d_in, const int* in_sizes, int n_in,
                              void* d_out, int out_size)
{
    const float* img = (const float*)d_in[0];
    const float* psx = (const float*)d_in[1];
    const float* psy = (const float*)d_in[2];
    const float* psz = (const float*)d_in[3];
    const float* pcs = (const float*)d_in[4];
    float* outp = (float*)d_out;

    const int batches = in_sizes[0] / NVOX;
    dim3 block(TX, TY, TZ);
    dim3 grid(NDIM / TX, NDIM / TY, (NDIM / TZ) * batches);
    bilateral3d_kernel<<<grid, block>>>(img, outp, psx, psy, psz, pcs);
}